// round 6
// baseline (speedup 1.0000x reference)
#include <cuda_runtime.h>

#define B_DIM   256
#define OUT_DIM 256
#define IN_DIM  256
#define G_DIM   8
#define LOG2E   1.44269504088896340736f
#define LN2     0.69314718055994530942f

#define OT     8          // o per CTA
#define BT     32         // b per CTA
#define PAIRS  16         // b-pairs per CTA
#define NTHR   128
#define IC     32         // i-chunk
#define ZSPLIT 2          // i halves across gridDim.z
#define IHALF  (IN_DIM / ZSPLIT)
#define NCH    (IHALF / IC)       // 4 chunks per CTA
#define ABROW  20         // floats per (ii,oo) cell: A0,B0..A8,B8,s,base*ln2
#define IISTR  162        // floats per ii slice (8*20 + 2 pad); 162 mod 32 = 2
#define XNSTR  34         // xn row stride in floats (pad, 8B-aligned pairs)

__device__ __forceinline__ float rcp_f(float a) {
    float r; asm("rcp.approx.f32 %0, %1;" : "=f"(r) : "f"(a)); return r;
}
__device__ __forceinline__ float ex2_f(float a) {
    float r; asm("ex2.approx.f32 %0, %1;" : "=f"(r) : "f"(a)); return r;
}
__device__ __forceinline__ float tanh_fast(float x) {
    float e = __expf(2.0f * x);                 // saturates correctly at +/-inf
    return 1.0f - __fdividef(2.0f, e + 1.0f);
}

__global__ __launch_bounds__(NTHR, 4)
void k_fused(const float* __restrict__ x,
             const float* __restrict__ w,
             const float* __restrict__ scaler,
             const float* __restrict__ base_,
             const float* __restrict__ grid,
             float* __restrict__ out)
{
    __shared__ float         sh_xn[IC][XNSTR];   // xn * log2e
    __shared__ unsigned char sh_kb[IC][32];      // koff = k*8 (byte offset into cell)
    __shared__ float         sh_ab[IC * IISTR];

    const int tid   = threadIdx.x;
    const int o0    = blockIdx.x * OT;
    const int b0    = blockIdx.y * BT;
    const int ibase = blockIdx.z * IHALF;

    // consumer roles
    const int o_local = tid & (OT - 1);
    const int pair    = tid >> 3;               // 0..15 -> b = 2*pair, 2*pair+1
    // x-prep roles: thread loads 8 consecutive i for one b
    const int xb  = tid >> 2;                   // 0..31
    const int xi8 = (tid & 3) * 8;              // 0,8,16,24
    // AB-prep roles: 2 cells/thread: (iiA, ooA) and (iiA, ooA+4)
    const int iiA = tid & 31;
    const int ooA = tid >> 5;                   // 0..3

    const float g0    = __ldg(grid);
    const float g7    = __ldg(grid + (G_DIM - 1));
    const float step  = (g7 - g0) * (1.0f / (float)(G_DIM - 1));
    const float inv_h = (float)(G_DIM - 1) / (g7 - g0);

    // ---- prefetch chunk 0 ----
    const float* xrow = x + (b0 + xb) * IN_DIM + ibase + xi8;
    float4 xq0 = *(const float4*)(xrow);
    float4 xq1 = *(const float4*)(xrow + 4);
    int rowA = (o0 + ooA) * IN_DIM + ibase + iiA;
    int rowB = rowA + 4 * IN_DIM;
    float4 wa0 = *(const float4*)(w + rowA * G_DIM);
    float4 wa1 = *(const float4*)(w + rowA * G_DIM + 4);
    float4 wb0 = *(const float4*)(w + rowB * G_DIM);
    float4 wb1 = *(const float4*)(w + rowB * G_DIM + 4);
    float  sA = scaler[rowA], sB = scaler[rowB];
    float  bA = base_[rowA],  bB = base_[rowB];

    float acc0 = 0.f, acc1 = 0.f;

#pragma unroll 1
    for (int c = 0; c < NCH; c++) {
        // ---- xn/k for this chunk (from regs) ----
        {
            float xv[8] = {xq0.x, xq0.y, xq0.z, xq0.w, xq1.x, xq1.y, xq1.z, xq1.w};
#pragma unroll
            for (int v = 0; v < 8; v++) {
                float xn = tanh_fast(xv[v]);
                int k = 1 + __float2int_rd((xn - g0) * inv_h);
                k = max(0, min(8, k));
                sh_xn[xi8 + v][xb] = xn * LOG2E;
                sh_kb[xi8 + v][xb] = (unsigned char)(k * 8);
            }
        }
        // ---- A/B prefix tables: 2 cells per thread (from regs) ----
#pragma unroll
        for (int cc = 0; cc < 2; cc++) {
            float4 wlo = cc ? wb0 : wa0;
            float4 whi = cc ? wb1 : wa1;
            float  s   = cc ? sB  : sA;
            float  bse = cc ? bB  : bA;
            float wv[G_DIM] = {wlo.x, wlo.y, wlo.z, wlo.w, whi.x, whi.y, whi.z, whi.w};
            float Ep = __expf(s * step);
            float ep = __expf(s * g0);
            float Eq = rcp_f(Ep);
            float eq = rcp_f(ep);
            float p[G_DIM], q[G_DIM];
#pragma unroll
            for (int g = 0; g < G_DIM; g++) {
                p[g] = wv[g] * ep;  ep *= Ep;
                q[g] = wv[g] * eq;  eq *= Eq;
            }
            float A[9], Bv[9];
            A[0] = 0.f;
#pragma unroll
            for (int k = 0; k < 8; k++) A[k + 1] = A[k] + p[k];
            Bv[8] = 0.f;
#pragma unroll
            for (int k = 7; k >= 0; k--) Bv[k] = Bv[k + 1] + q[k];

            float2* cell = (float2*)(sh_ab + iiA * IISTR + (ooA + 4 * cc) * ABROW);
#pragma unroll
            for (int k = 0; k < 9; k++) cell[k] = make_float2(A[k], Bv[k]);
            cell[9] = make_float2(s, bse * LN2);
        }

        // ---- prefetch next chunk ----
        if (c + 1 < NCH) {
            const float* xn2p = xrow + (c + 1) * IC;
            xq0 = *(const float4*)(xn2p);
            xq1 = *(const float4*)(xn2p + 4);
            int rA = rowA + (c + 1) * IC;
            int rB = rowB + (c + 1) * IC;
            wa0 = *(const float4*)(w + rA * G_DIM);
            wa1 = *(const float4*)(w + rA * G_DIM + 4);
            wb0 = *(const float4*)(w + rB * G_DIM);
            wb1 = *(const float4*)(w + rB * G_DIM + 4);
            sA = scaler[rA]; sB = scaler[rB];
            bA = base_[rA];  bB = base_[rB];
        }
        __syncthreads();

        // ---- consume: 2 triples per iter per thread ----
        const float* cellp = sh_ab + o_local * ABROW;
        const char*  kbase = (const char*)&sh_kb[0][0] + 2 * pair;
#pragma unroll
        for (int ii = 0; ii < IC; ii++) {
            float2 xn2 = *(const float2*)&sh_xn[ii][2 * pair];
            unsigned int kk = *(const unsigned short*)(kbase + ii * 32);
            const char* cp = (const char*)(cellp + ii * IISTR);
            float2 sb = *(const float2*)(cp + 72);
            float2 a0 = *(const float2*)(cp + (kk & 0xFFu));
            float2 a1 = *(const float2*)(cp + (kk >> 8));
            float t0 = sb.x * xn2.x;
            float t1 = sb.x * xn2.y;
            float u0 = ex2_f(t0), r0 = rcp_f(u0);
            float u1 = ex2_f(t1), r1 = rcp_f(u1);
            acc0 = fmaf(a0.x, r0, fmaf(a0.y, u0, fmaf(sb.y, xn2.x, acc0)));
            acc1 = fmaf(a1.x, r1, fmaf(a1.y, u1, fmaf(sb.y, xn2.y, acc1)));
        }
        __syncthreads();
    }

    // combine the two i-halves: exactly 2 commutative adds from 0 -> deterministic
    int ob = (b0 + 2 * pair) * OUT_DIM + o0 + o_local;
    atomicAdd(out + ob, acc0);
    atomicAdd(out + ob + OUT_DIM, acc1);
}

// ---------------------------------------------------------------------------
extern "C" void kernel_launch(void* const* d_in, const int* in_sizes, int n_in,
                              void* d_out, int out_size)
{
    const float* x      = (const float*)d_in[0];
    const float* w      = (const float*)d_in[1];
    const float* scaler = (const float*)d_in[2];
    const float* base   = (const float*)d_in[3];
    const float* grid   = (const float*)d_in[4];
    float* out = (float*)d_out;

    cudaMemsetAsync(out, 0, (size_t)out_size * sizeof(float));
    dim3 g(OUT_DIM / OT, B_DIM / BT, ZSPLIT);   // 32 x 8 x 2 = 512 CTAs
    k_fused<<<g, NTHR>>>(x, w, scaler, base, grid, out);
}